// round 2
// baseline (speedup 1.0000x reference)
#include <cuda_runtime.h>

// Problem constants
#define EE   512
#define HH   8
#define DD   64
#define BBSZ 32
#define PPN  512
#define SSN  1024

// Scratch (device globals; no allocation allowed)
__device__ float g_Q[BBSZ * PPN * EE];    // projected Q  [B*P, E]
__device__ float g_K[BBSZ * SSN * EE];    // projected K  [B*S, E]
__device__ float g_V[BBSZ * SSN * EE];    // projected V  [B*S, E]
__device__ float g_ctx[BBSZ * PPN * EE];  // attention output [B*P, E]

// ---------------------------------------------------------------------------
// C[M,512] = A[M,512] @ W[512,512]^T (+ bias)   (NT gemm, both K-contiguous)
// Tile: BM=128, BN=128, BK=16; 256 threads; 8x8 micro-tile per thread.
// ---------------------------------------------------------------------------
__global__ __launch_bounds__(256) void sgemm_nt(
    const float* __restrict__ A, const float* __restrict__ W,
    const float* __restrict__ bias, float* __restrict__ C, int M)
{
    __shared__ float As[16][132];
    __shared__ float Bs[16][132];

    const int tid = threadIdx.x;
    const int tr = tid >> 4;       // 0..15
    const int tc = tid & 15;       // 0..15
    const int m0 = blockIdx.y * 128;
    const int n0 = blockIdx.x * 128;

    float acc[8][8];
#pragma unroll
    for (int i = 0; i < 8; i++)
#pragma unroll
        for (int j = 0; j < 8; j++) acc[i][j] = 0.f;

    const float4* A4 = (const float4*)A;
    const float4* W4 = (const float4*)W;

    for (int k0 = 0; k0 < 512; k0 += 16) {
#pragma unroll
        for (int q = 0; q < 2; q++) {
            int f = tid + q * 256;          // 0..511 float4s
            int r = f >> 2;                 // 0..127
            int c4 = f & 3;                 // 0..3
            float4 va = A4[(size_t)(m0 + r) * 128 + (k0 >> 2) + c4];
            As[c4 * 4 + 0][r] = va.x; As[c4 * 4 + 1][r] = va.y;
            As[c4 * 4 + 2][r] = va.z; As[c4 * 4 + 3][r] = va.w;
            float4 vb = W4[(size_t)(n0 + r) * 128 + (k0 >> 2) + c4];
            Bs[c4 * 4 + 0][r] = vb.x; Bs[c4 * 4 + 1][r] = vb.y;
            Bs[c4 * 4 + 2][r] = vb.z; Bs[c4 * 4 + 3][r] = vb.w;
        }
        __syncthreads();

#pragma unroll
        for (int kk = 0; kk < 16; kk++) {
            float4 a0 = *(const float4*)&As[kk][tr * 8];
            float4 a1 = *(const float4*)&As[kk][tr * 8 + 4];
            float4 b0 = *(const float4*)&Bs[kk][tc * 8];
            float4 b1 = *(const float4*)&Bs[kk][tc * 8 + 4];
            float a[8] = {a0.x, a0.y, a0.z, a0.w, a1.x, a1.y, a1.z, a1.w};
            float b[8] = {b0.x, b0.y, b0.z, b0.w, b1.x, b1.y, b1.z, b1.w};
#pragma unroll
            for (int i = 0; i < 8; i++)
#pragma unroll
                for (int j = 0; j < 8; j++) acc[i][j] += a[i] * b[j];
        }
        __syncthreads();
    }

    float bj[8];
#pragma unroll
    for (int j = 0; j < 8; j++) bj[j] = bias ? bias[n0 + tc * 8 + j] : 0.f;

#pragma unroll
    for (int i = 0; i < 8; i++) {
        size_t row = (size_t)(m0 + tr * 8 + i);
        float4 o0 = {acc[i][0] + bj[0], acc[i][1] + bj[1],
                     acc[i][2] + bj[2], acc[i][3] + bj[3]};
        float4 o1 = {acc[i][4] + bj[4], acc[i][5] + bj[5],
                     acc[i][6] + bj[6], acc[i][7] + bj[7]};
        *(float4*)&C[row * 512 + n0 + tc * 8]     = o0;
        *(float4*)&C[row * 512 + n0 + tc * 8 + 4] = o1;
    }
}

// ---------------------------------------------------------------------------
// Flash attention. One block = (b, h, 64 query rows). 256 threads.
// S-tiles of 64; online softmax; acc 4x4 per thread (16x16 thread grid).
// Mask arrives as int32 [B,P,S] (bool -> int32 in harness); packed to uchar
// in smem. Masked scores use -1e30 sentinel.
// ---------------------------------------------------------------------------
#define APAD 68
#define SMEM_ATTN ((4 * 64 * APAD + 3 * 64) * 4 + 64 * 64)

__global__ __launch_bounds__(256) void flash_attn(
    const float* __restrict__ Qp, const float* __restrict__ Kp,
    const float* __restrict__ Vp, const int* __restrict__ mask,
    float* __restrict__ ctx)
{
    extern __shared__ float sm[];
    float* Qs = sm;                         // [64][APAD]
    float* Ks = Qs + 64 * APAD;
    float* Vs = Ks + 64 * APAD;
    float* Ps = Vs + 64 * APAD;             // scores / probs
    float* mrow = Ps + 64 * APAD;           // [64]
    float* lrow = mrow + 64;
    float* frow = lrow + 64;
    unsigned char* msk = (unsigned char*)(frow + 64);   // [64][64]

    const int tid = threadIdx.x;
    const int bh = blockIdx.y;              // b*H + h
    const int b = bh >> 3;
    const int h = bh & 7;
    const int p0 = blockIdx.x * 64;
    const int tr = tid >> 4;                // 0..15
    const int tc = tid & 15;                // 0..15

    const float4* Q4 = (const float4*)Qp;
    const float4* K4 = (const float4*)Kp;
    const float4* V4 = (const float4*)Vp;
    const int4*   M4 = (const int4*)mask;

    // Q tile (once)
#pragma unroll
    for (int q = 0; q < 4; q++) {
        int f = tid + q * 256;              // 0..1023
        int r = f >> 4, d4 = f & 15;
        float4 v = Q4[(size_t)(b * PPN + p0 + r) * 128 + h * 16 + d4];
        *(float4*)&Qs[r * APAD + d4 * 4] = v;
    }
    if (tid < 64) { mrow[tid] = -1e30f; lrow[tid] = 0.f; frow[tid] = 0.f; }

    float acc[4][4];
#pragma unroll
    for (int i = 0; i < 4; i++)
#pragma unroll
        for (int j = 0; j < 4; j++) acc[i][j] = 0.f;

    for (int s0 = 0; s0 < SSN; s0 += 64) {
        __syncthreads();   // previous iteration finished with Ks/Vs/Ps/msk

        // load K, V tiles
#pragma unroll
        for (int q = 0; q < 4; q++) {
            int f = tid + q * 256;
            int r = f >> 4, d4 = f & 15;
            *(float4*)&Ks[r * APAD + d4 * 4] =
                K4[(size_t)(b * SSN + s0 + r) * 128 + h * 16 + d4];
            *(float4*)&Vs[r * APAD + d4 * 4] =
                V4[(size_t)(b * SSN + s0 + r) * 128 + h * 16 + d4];
        }
        // mask tile: int32 [64 rows][64 cols] -> uchar smem.
        // 64*64 ints = 1024 int4; 4 per thread. Row stride = S = 1024 ints = 256 int4.
#pragma unroll
        for (int q = 0; q < 4; q++) {
            int f = tid + q * 256;          // 0..1023
            int r = f >> 4, c4 = f & 15;    // c4: 16 int4 = 64 ints per row
            int4 m = M4[(size_t)(b * PPN + p0 + r) * 256 + (s0 >> 2) + c4];
            msk[r * 64 + c4 * 4 + 0] = (unsigned char)m.x;
            msk[r * 64 + c4 * 4 + 1] = (unsigned char)m.y;
            msk[r * 64 + c4 * 4 + 2] = (unsigned char)m.z;
            msk[r * 64 + c4 * 4 + 3] = (unsigned char)m.w;
        }
        __syncthreads();

        // scores: 4x4 per thread, K-dim = 64
        float sc[4][4];
#pragma unroll
        for (int i = 0; i < 4; i++)
#pragma unroll
            for (int j = 0; j < 4; j++) sc[i][j] = 0.f;

#pragma unroll
        for (int d4 = 0; d4 < 16; d4++) {
            float4 qa[4], kb[4];
#pragma unroll
            for (int i = 0; i < 4; i++)
                qa[i] = *(const float4*)&Qs[(tr * 4 + i) * APAD + d4 * 4];
#pragma unroll
            for (int j = 0; j < 4; j++)
                kb[j] = *(const float4*)&Ks[(tc * 4 + j) * APAD + d4 * 4];
#pragma unroll
            for (int i = 0; i < 4; i++)
#pragma unroll
                for (int j = 0; j < 4; j++)
                    sc[i][j] += qa[i].x * kb[j].x + qa[i].y * kb[j].y +
                                qa[i].z * kb[j].z + qa[i].w * kb[j].w;
        }
        const float scale = 0.125f;   // 1/sqrt(64)
#pragma unroll
        for (int i = 0; i < 4; i++)
#pragma unroll
            for (int j = 0; j < 4; j++) {
                float v = sc[i][j] * scale;
                if (msk[(tr * 4 + i) * 64 + tc * 4 + j]) v = -1e30f;
                Ps[(tr * 4 + i) * APAD + tc * 4 + j] = v;
            }
        __syncthreads();

        // online-softmax stats: 4 threads per row
        {
            int r = tid >> 2, ln = tid & 3;
            float4* Pr = (float4*)&Ps[r * APAD];
            float4 v[4];
            float mx = -1e30f;
#pragma unroll
            for (int q = 0; q < 4; q++) {
                v[q] = Pr[ln * 4 + q];
                mx = fmaxf(mx, fmaxf(fmaxf(v[q].x, v[q].y), fmaxf(v[q].z, v[q].w)));
            }
            mx = fmaxf(mx, __shfl_xor_sync(0xffffffffu, mx, 1));
            mx = fmaxf(mx, __shfl_xor_sync(0xffffffffu, mx, 2));
            float m_old = mrow[r];
            float m_new = fmaxf(m_old, mx);
            float fct = __expf(m_old - m_new);
            float sum = 0.f;
#pragma unroll
            for (int q = 0; q < 4; q++) {
                v[q].x = __expf(v[q].x - m_new);
                v[q].y = __expf(v[q].y - m_new);
                v[q].z = __expf(v[q].z - m_new);
                v[q].w = __expf(v[q].w - m_new);
                sum += v[q].x + v[q].y + v[q].z + v[q].w;
                Pr[ln * 4 + q] = v[q];
            }
            sum += __shfl_xor_sync(0xffffffffu, sum, 1);
            sum += __shfl_xor_sync(0xffffffffu, sum, 2);
            if (ln == 0) {
                mrow[r] = m_new;
                lrow[r] = fct * lrow[r] + sum;
                frow[r] = fct;
            }
        }
        __syncthreads();

        // ctx accumulate:  O[r][d] = f*O + P @ V
#pragma unroll
        for (int i = 0; i < 4; i++) {
            float fct = frow[tr * 4 + i];
#pragma unroll
            for (int j = 0; j < 4; j++) acc[i][j] *= fct;
        }
        for (int s = 0; s < 64; s++) {
            float4 v = *(const float4*)&Vs[s * APAD + tc * 4];
#pragma unroll
            for (int i = 0; i < 4; i++) {
                float p = Ps[(tr * 4 + i) * APAD + s];
                acc[i][0] += p * v.x; acc[i][1] += p * v.y;
                acc[i][2] += p * v.z; acc[i][3] += p * v.w;
            }
        }
    }

    // finalize: divide by l, write ctx[B*P, E]
#pragma unroll
    for (int i = 0; i < 4; i++) {
        int r = tr * 4 + i;
        float inv = 1.f / lrow[r];
        float4 o = {acc[i][0] * inv, acc[i][1] * inv,
                    acc[i][2] * inv, acc[i][3] * inv};
        *(float4*)&ctx[(size_t)(b * PPN + p0 + r) * EE + h * 64 + tc * 4] = o;
    }
}

// ---------------------------------------------------------------------------
extern "C" void kernel_launch(void* const* d_in, const int* in_sizes, int n_in,
                              void* d_out, int out_size)
{
    const float* query = (const float*)d_in[0];
    const float* key   = (const float*)d_in[1];
    const float* value = (const float*)d_in[2];
    const int*   mask  = (const int*)d_in[3];
    const float* Wq = (const float*)d_in[4];
    const float* Wk = (const float*)d_in[5];
    const float* Wv = (const float*)d_in[6];
    const float* Wo = (const float*)d_in[7];
    const float* bo = (const float*)d_in[8];
    float* out = (float*)d_out;

    float *qp, *kp, *vp, *cx;
    cudaGetSymbolAddress((void**)&qp, g_Q);
    cudaGetSymbolAddress((void**)&kp, g_K);
    cudaGetSymbolAddress((void**)&vp, g_V);
    cudaGetSymbolAddress((void**)&cx, g_ctx);

    cudaFuncSetAttribute(flash_attn,
                         cudaFuncAttributeMaxDynamicSharedMemorySize,
                         SMEM_ATTN);

    dim3 blk(256);
    dim3 gq(4, 128);    // M = 32*512   = 16384
    dim3 gkv(4, 256);   // M = 32*1024  = 32768

    sgemm_nt<<<gq,  blk>>>(query, Wq, nullptr, qp, BBSZ * PPN);
    sgemm_nt<<<gkv, blk>>>(key,   Wk, nullptr, kp, BBSZ * SSN);
    sgemm_nt<<<gkv, blk>>>(value, Wv, nullptr, vp, BBSZ * SSN);

    flash_attn<<<dim3(PPN / 64, BBSZ * HH), blk, SMEM_ATTN>>>(qp, kp, vp, mask, cx);

    sgemm_nt<<<gq, blk>>>(cx, Wo, bo, out, BBSZ * PPN);
}

// round 4
// speedup vs baseline: 1.1829x; 1.1829x over previous
#include <cuda_runtime.h>
#include <cuda_bf16.h>
#include <cstdint>

// Problem constants
#define EE   512
#define HH   8
#define BBSZ 32
#define PPN  512
#define SSN  1024
#define MQ   (BBSZ * PPN)    // 16384
#define MKV  (BBSZ * SSN)    // 32768

// ---------------------------------------------------------------------------
// Scratch (device globals; no allocation allowed)
// ---------------------------------------------------------------------------
__device__ __align__(16) float g_Q[MQ * EE];
__device__ __align__(16) float g_K[MKV * EE];
__device__ __align__(16) float g_V[MKV * EE];
__device__ __align__(16) float g_ctx[MQ * EE];
__device__ __align__(16) __nv_bfloat16 g_act_hi[MKV * EE];  // reused per GEMM
__device__ __align__(16) __nv_bfloat16 g_act_lo[MKV * EE];
__device__ __align__(16) __nv_bfloat16 g_w_hi[4][EE * EE];
__device__ __align__(16) __nv_bfloat16 g_w_lo[4][EE * EE];

// ---------------------------------------------------------------------------
// fp32 -> bf16 hi/lo split (vectorized x4)
// ---------------------------------------------------------------------------
__global__ void convert_split(const float* __restrict__ X,
                              __nv_bfloat16* __restrict__ H,
                              __nv_bfloat16* __restrict__ L, int n4)
{
    int i = blockIdx.x * blockDim.x + threadIdx.x;
    if (i >= n4) return;
    float4 x = ((const float4*)X)[i];
    __nv_bfloat16 h0 = __float2bfloat16(x.x);
    __nv_bfloat16 h1 = __float2bfloat16(x.y);
    __nv_bfloat16 h2 = __float2bfloat16(x.z);
    __nv_bfloat16 h3 = __float2bfloat16(x.w);
    __nv_bfloat16 l0 = __float2bfloat16(x.x - __bfloat162float(h0));
    __nv_bfloat16 l1 = __float2bfloat16(x.y - __bfloat162float(h1));
    __nv_bfloat16 l2 = __float2bfloat16(x.z - __bfloat162float(h2));
    __nv_bfloat16 l3 = __float2bfloat16(x.w - __bfloat162float(h3));
    __nv_bfloat162* H2 = (__nv_bfloat162*)H;
    __nv_bfloat162* L2 = (__nv_bfloat162*)L;
    H2[2 * i]     = __nv_bfloat162{h0, h1};
    H2[2 * i + 1] = __nv_bfloat162{h2, h3};
    L2[2 * i]     = __nv_bfloat162{l0, l1};
    L2[2 * i + 1] = __nv_bfloat162{l2, l3};
}

// ---------------------------------------------------------------------------
// mma.sync helpers (baseline sm_80+ features only; compile under compute_103)
// ---------------------------------------------------------------------------
__device__ __forceinline__ uint32_t smem_u32(const void* p) {
    uint32_t a;
    asm("{ .reg .u64 t; cvta.to.shared.u64 t, %1; cvt.u32.u64 %0, t; }"
        : "=r"(a) : "l"(p));
    return a;
}
__device__ __forceinline__ void ldsm_x4(uint32_t& r0, uint32_t& r1,
                                        uint32_t& r2, uint32_t& r3, uint32_t a) {
    asm volatile("ldmatrix.sync.aligned.m8n8.x4.shared.b16 {%0,%1,%2,%3}, [%4];"
                 : "=r"(r0), "=r"(r1), "=r"(r2), "=r"(r3) : "r"(a));
}
__device__ __forceinline__ void mma_bf16(float* c, const uint32_t* a,
                                         uint32_t b0, uint32_t b1) {
    asm volatile(
        "mma.sync.aligned.m16n8k16.row.col.f32.bf16.bf16.f32 "
        "{%0,%1,%2,%3}, {%4,%5,%6,%7}, {%8,%9}, {%0,%1,%2,%3};"
        : "+f"(c[0]), "+f"(c[1]), "+f"(c[2]), "+f"(c[3])
        : "r"(a[0]), "r"(a[1]), "r"(a[2]), "r"(a[3]), "r"(b0), "r"(b1));
}
__device__ __forceinline__ void cp16(uint32_t dst, const void* src) {
    asm volatile("cp.async.cg.shared.global [%0], [%1], 16;"
                 :: "r"(dst), "l"(src) : "memory");
}

// ---------------------------------------------------------------------------
// Tensor-core GEMM: C[M,512] = A[M,512] @ W[512,512]^T (+bias)
// fp32 via bf16 3-term split, K-concat (K_eff = 1536):
//   seg0 = Ahi*Whi, seg1 = Ahi*Wlo, seg2 = Alo*Whi
// CTA 128x128, 8 warps (2x4), warp tile 64x32, K-chunk 64, double buffered.
// ---------------------------------------------------------------------------
#define GSM 65536   // 2 stages x (16KB A + 16KB B)

__global__ __launch_bounds__(256) void gemm_mma(
    const __nv_bfloat16* __restrict__ Ahi, const __nv_bfloat16* __restrict__ Alo,
    const __nv_bfloat16* __restrict__ Whi, const __nv_bfloat16* __restrict__ Wlo,
    const float* __restrict__ bias, float* __restrict__ C)
{
    extern __shared__ char smem[];
    const uint32_t sb = smem_u32(smem);
    const int tid = threadIdx.x;
    const int wid = tid >> 5;
    const int lane = tid & 31;
    const int wm = wid >> 2;          // 0..1
    const int wn = wid & 3;           // 0..3
    const int m0 = blockIdx.y * 128;
    const int n0 = blockIdx.x * 128;

    // store addressing: thread covers 64B of one 128B row
    const int r = tid >> 1;
    const int half = tid & 1;
    uint32_t so[4];
#pragma unroll
    for (int i = 0; i < 4; i++) {
        uint32_t bo = (uint32_t)r * 128 + half * 64 + i * 16;
        so[i] = bo ^ ((bo >> 3) & 0x70);
    }

    // ldmatrix addressing constants
    const int lrow = lane & 15;              // row within 16-row frag
    const uint32_t kxor = (uint32_t)(lane & 7) << 4;
    const uint32_t khalf = (uint32_t)(lane >> 4) * 16;   // +16B for k+8

    float acc[4][4][4];
#pragma unroll
    for (int i = 0; i < 4; i++)
#pragma unroll
        for (int f = 0; f < 4; f++)
#pragma unroll
            for (int c = 0; c < 4; c++) acc[i][f][c] = 0.f;

    auto issue_load = [&](int kc, int buf) {
        const int seg = kc >> 3;
        const int kb = (kc & 7) * 64;
        const __nv_bfloat16* Asrc = (seg == 2) ? Alo : Ahi;
        const __nv_bfloat16* Wsrc = (seg == 1) ? Wlo : Whi;
        const char* ag = (const char*)(Asrc + (size_t)(m0 + r) * 512 + kb) + half * 64;
        const char* bg = (const char*)(Wsrc + (size_t)(n0 + r) * 512 + kb) + half * 64;
        uint32_t abase = sb + buf * 32768;
        uint32_t bbase = abase + 16384;
#pragma unroll
        for (int i = 0; i < 4; i++) {
            cp16(abase + so[i], ag + i * 16);
            cp16(bbase + so[i], bg + i * 16);
        }
        asm volatile("cp.async.commit_group;" ::: "memory");
    };

    issue_load(0, 0);

    for (int kc = 0; kc < 24; kc++) {
        const int buf = kc & 1;
        if (kc < 23) issue_load(kc + 1, buf ^ 1);
        if (kc < 23) asm volatile("cp.async.wait_group 1;" ::: "memory");
        else         asm volatile("cp.async.wait_group 0;" ::: "memory");
        __syncthreads();

        const uint32_t abase = sb + buf * 32768;
        const uint32_t bbase = abase + 16384;
#pragma unroll
        for (int ks = 0; ks < 4; ks++) {
            const uint32_t kpart = ((uint32_t)(ks * 32) + khalf) ^ kxor;
            uint32_t a[4][4];
#pragma unroll
            for (int im = 0; im < 4; im++) {
                uint32_t addr = abase + (uint32_t)(wm * 64 + im * 16 + lrow) * 128 + kpart;
                ldsm_x4(a[im][0], a[im][1], a[im][2], a[im][3], addr);
            }
            uint32_t b[2][4];
#pragma unroll
            for (int nb = 0; nb < 2; nb++) {
                uint32_t addr = bbase + (uint32_t)(wn * 32 + nb * 16 + lrow) * 128 + kpart;
                ldsm_x4(b[nb][0], b[nb][1], b[nb][2], b[nb][3], addr);
            }
#pragma unroll
            for (int im = 0; im < 4; im++)
#pragma unroll
                for (int f = 0; f < 4; f++)
                    mma_bf16(acc[im][f], a[im],
                             b[f >> 1][f & 1], b[f >> 1][(f & 1) + 2]);
        }
        __syncthreads();
    }

    // epilogue: C[row][col] (+bias)
    const int crow = lane >> 2;
    const int ccol = (lane & 3) * 2;
#pragma unroll
    for (int im = 0; im < 4; im++) {
#pragma unroll
        for (int f = 0; f < 4; f++) {
            int row = m0 + wm * 64 + im * 16 + crow;
            int col = n0 + wn * 32 + (f >> 1) * 16 + (f & 1) * 8 + ccol;
            float b0 = bias ? bias[col] : 0.f;
            float b1 = bias ? bias[col + 1] : 0.f;
            float2 v0 = {acc[im][f][0] + b0, acc[im][f][1] + b1};
            float2 v1 = {acc[im][f][2] + b0, acc[im][f][3] + b1};
            *(float2*)&C[(size_t)row * 512 + col] = v0;
            *(float2*)&C[(size_t)(row + 8) * 512 + col] = v1;
        }
    }
}

// ---------------------------------------------------------------------------
// Flash attention (fp32). One block = (b, h, 64 query rows). 256 threads.
// Mask arrives as int32 [B,P,S]; packed to uchar in smem.
// ---------------------------------------------------------------------------
#define APAD 68
#define SMEM_ATTN ((4 * 64 * APAD + 3 * 64) * 4 + 64 * 64)

__global__ __launch_bounds__(256) void flash_attn(
    const float* __restrict__ Qp, const float* __restrict__ Kp,
    const float* __restrict__ Vp, const int* __restrict__ mask,
    float* __restrict__ ctx)
{
    extern __shared__ float sm[];
    float* Qs = sm;                         // [64][APAD]
    float* Ks = Qs + 64 * APAD;
    float* Vs = Ks + 64 * APAD;
    float* Ps = Vs + 64 * APAD;
    float* mrow = Ps + 64 * APAD;           // [64]
    float* lrow = mrow + 64;
    float* frow = lrow + 64;
    unsigned char* msk = (unsigned char*)(frow + 64);   // [64][64]

    const int tid = threadIdx.x;
    const int bh = blockIdx.y;
    const int b = bh >> 3;
    const int h = bh & 7;
    const int p0 = blockIdx.x * 64;
    const int tr = tid >> 4;
    const int tc = tid & 15;

    const float4* Q4 = (const float4*)Qp;
    const float4* K4 = (const float4*)Kp;
    const float4* V4 = (const float4*)Vp;
    const int4*   M4 = (const int4*)mask;

#pragma unroll
    for (int q = 0; q < 4; q++) {
        int f = tid + q * 256;
        int rr = f >> 4, d4 = f & 15;
        float4 v = Q4[(size_t)(b * PPN + p0 + rr) * 128 + h * 16 + d4];
        *(float4*)&Qs[rr * APAD + d4 * 4] = v;
    }
    if (tid < 64) { mrow[tid] = -1e30f; lrow[tid] = 0.f; frow[tid] = 0.f; }

    float acc[4][4];
#pragma unroll
    for (int i = 0; i < 4; i++)
#pragma unroll
        for (int j = 0; j < 4; j++) acc[i][j] = 0.f;

    for (int s0 = 0; s0 < SSN; s0 += 64) {
        __syncthreads();

#pragma unroll
        for (int q = 0; q < 4; q++) {
            int f = tid + q * 256;
            int rr = f >> 4, d4 = f & 15;
            *(float4*)&Ks[rr * APAD + d4 * 4] =
                K4[(size_t)(b * SSN + s0 + rr) * 128 + h * 16 + d4];
            *(float4*)&Vs[rr * APAD + d4 * 4] =
                V4[(size_t)(b * SSN + s0 + rr) * 128 + h * 16 + d4];
        }
#pragma unroll
        for (int q = 0; q < 4; q++) {
            int f = tid + q * 256;
            int rr = f >> 4, c4 = f & 15;
            int4 m = M4[(size_t)(b * PPN + p0 + rr) * 256 + (s0 >> 2) + c4];
            msk[rr * 64 + c4 * 4 + 0] = (unsigned char)m.x;
            msk[rr * 64 + c4 * 4 + 1] = (unsigned char)m.y;
            msk[rr * 64 + c4 * 4 + 2] = (unsigned char)m.z;
            msk[rr * 64 + c4 * 4 + 3] = (unsigned char)m.w;
        }
        __syncthreads();

        float sc[4][4];
#pragma unroll
        for (int i = 0; i < 4; i++)
#pragma unroll
            for (int j = 0; j < 4; j++) sc[i][j] = 0.f;

#pragma unroll
        for (int d4 = 0; d4 < 16; d4++) {
            float4 qa[4], kb[4];
#pragma unroll
            for (int i = 0; i < 4; i++)
                qa[i] = *(const float4*)&Qs[(tr * 4 + i) * APAD + d4 * 4];
#pragma unroll
            for (int j = 0; j < 4; j++)
                kb[j] = *(const float4*)&Ks[(tc * 4 + j) * APAD + d4 * 4];
#pragma unroll
            for (int i = 0; i < 4; i++)
#pragma unroll
                for (int j = 0; j < 4; j++)
                    sc[i][j] += qa[i].x * kb[j].x + qa[i].y * kb[j].y +
                                qa[i].z * kb[j].z + qa[i].w * kb[j].w;
        }
        const float scale = 0.125f;
#pragma unroll
        for (int i = 0; i < 4; i++)
#pragma unroll
            for (int j = 0; j < 4; j++) {
                float v = sc[i][j] * scale;
                if (msk[(tr * 4 + i) * 64 + tc * 4 + j]) v = -1e30f;
                Ps[(tr * 4 + i) * APAD + tc * 4 + j] = v;
            }
        __syncthreads();

        {
            int rr = tid >> 2, ln = tid & 3;
            float4* Pr = (float4*)&Ps[rr * APAD];
            float4 v[4];
            float mx = -1e30f;
#pragma unroll
            for (int q = 0; q < 4; q++) {
                v[q] = Pr[ln * 4 + q];
                mx = fmaxf(mx, fmaxf(fmaxf(v[q].x, v[q].y), fmaxf(v[q].z, v[q].w)));
            }
            mx = fmaxf(mx, __shfl_xor_sync(0xffffffffu, mx, 1));
            mx = fmaxf(mx, __shfl_xor_sync(0xffffffffu, mx, 2));
            float m_old = mrow[rr];
            float m_new = fmaxf(m_old, mx);
            float fct = __expf(m_old - m_new);
            float sum = 0.f;
#pragma unroll
            for (int q = 0; q < 4; q++) {
                v[q].x = __expf(v[q].x - m_new);
                v[q].y = __expf(v[q].y - m_new);
                v[q].z = __expf(v[q].z - m_new);
                v[q].w = __expf(v[q].w - m_new);
                sum += v[q].x + v[q].y + v[q].z + v[q].w;
                Pr[ln * 4 + q] = v[q];
            }
            sum += __shfl_xor_sync(0xffffffffu, sum, 1);
            sum += __shfl_xor_sync(0xffffffffu, sum, 2);
            if (ln == 0) {
                mrow[rr] = m_new;
                lrow[rr] = fct * lrow[rr] + sum;
                frow[rr] = fct;
            }
        }
        __syncthreads();

#pragma unroll
        for (int i = 0; i < 4; i++) {
            float fct = frow[tr * 4 + i];
#pragma unroll
            for (int j = 0; j < 4; j++) acc[i][j] *= fct;
        }
        for (int s4 = 0; s4 < 64; s4 += 4) {
            float4 p[4];
#pragma unroll
            for (int i = 0; i < 4; i++)
                p[i] = *(const float4*)&Ps[(tr * 4 + i) * APAD + s4];
#pragma unroll
            for (int q = 0; q < 4; q++) {
                float4 v = *(const float4*)&Vs[(s4 + q) * APAD + tc * 4];
#pragma unroll
                for (int i = 0; i < 4; i++) {
                    float pp = (q == 0) ? p[i].x : (q == 1) ? p[i].y
                             : (q == 2) ? p[i].z : p[i].w;
                    acc[i][0] += pp * v.x; acc[i][1] += pp * v.y;
                    acc[i][2] += pp * v.z; acc[i][3] += pp * v.w;
                }
            }
        }
    }

#pragma unroll
    for (int i = 0; i < 4; i++) {
        int rr = tr * 4 + i;
        float inv = 1.f / lrow[rr];
        float4 o = {acc[i][0] * inv, acc[i][1] * inv,
                    acc[i][2] * inv, acc[i][3] * inv};
        *(float4*)&ctx[(size_t)(b * PPN + p0 + rr) * EE + h * 64 + tc * 4] = o;
    }
}

// ---------------------------------------------------------------------------
extern "C" void kernel_launch(void* const* d_in, const int* in_sizes, int n_in,
                              void* d_out, int out_size)
{
    const float* query = (const float*)d_in[0];
    const float* key   = (const float*)d_in[1];
    const float* value = (const float*)d_in[2];
    const int*   mask  = (const int*)d_in[3];
    const float* W[4]  = {(const float*)d_in[4], (const float*)d_in[5],
                          (const float*)d_in[6], (const float*)d_in[7]};
    const float* bo    = (const float*)d_in[8];
    float* out = (float*)d_out;

    float *qp, *kp, *vp, *cx;
    __nv_bfloat16 *ah, *al, *wh, *wl;
    cudaGetSymbolAddress((void**)&qp, g_Q);
    cudaGetSymbolAddress((void**)&kp, g_K);
    cudaGetSymbolAddress((void**)&vp, g_V);
    cudaGetSymbolAddress((void**)&cx, g_ctx);
    cudaGetSymbolAddress((void**)&ah, g_act_hi);
    cudaGetSymbolAddress((void**)&al, g_act_lo);
    cudaGetSymbolAddress((void**)&wh, g_w_hi);
    cudaGetSymbolAddress((void**)&wl, g_w_lo);

    cudaFuncSetAttribute(flash_attn, cudaFuncAttributeMaxDynamicSharedMemorySize,
                         SMEM_ATTN);
    cudaFuncSetAttribute(gemm_mma, cudaFuncAttributeMaxDynamicSharedMemorySize,
                         GSM);

    dim3 blk(256);

    // weight splits
    for (int w = 0; w < 4; w++)
        convert_split<<<(EE * EE / 4 + 255) / 256, 256>>>(
            W[w], wh + (size_t)w * EE * EE, wl + (size_t)w * EE * EE, EE * EE / 4);

    // Q proj
    convert_split<<<(MQ * EE / 4 + 255) / 256, 256>>>(query, ah, al, MQ * EE / 4);
    gemm_mma<<<dim3(4, MQ / 128), blk, GSM>>>(ah, al, wh, wl, nullptr, qp);
    // K proj
    convert_split<<<(MKV * EE / 4 + 255) / 256, 256>>>(key, ah, al, MKV * EE / 4);
    gemm_mma<<<dim3(4, MKV / 128), blk, GSM>>>(ah, al,
        wh + (size_t)1 * EE * EE, wl + (size_t)1 * EE * EE, nullptr, kp);
    // V proj
    convert_split<<<(MKV * EE / 4 + 255) / 256, 256>>>(value, ah, al, MKV * EE / 4);
    gemm_mma<<<dim3(4, MKV / 128), blk, GSM>>>(ah, al,
        wh + (size_t)2 * EE * EE, wl + (size_t)2 * EE * EE, nullptr, vp);

    flash_attn<<<dim3(PPN / 64, BBSZ * HH), blk, SMEM_ATTN>>>(qp, kp, vp, mask, cx);

    // O proj
    convert_split<<<(MQ * EE / 4 + 255) / 256, 256>>>(cx, ah, al, MQ * EE / 4);
    gemm_mma<<<dim3(4, MQ / 128), blk, GSM>>>(ah, al,
        wh + (size_t)3 * EE * EE, wl + (size_t)3 * EE * EE, bo, out);
}

// round 5
// speedup vs baseline: 2.6142x; 2.2100x over previous
#include <cuda_runtime.h>
#include <cuda_bf16.h>
#include <cstdint>

// Problem constants
#define EE   512
#define HH   8
#define BBSZ 32
#define PPN  512
#define SSN  1024
#define MQ   (BBSZ * PPN)    // 16384
#define MKV  (BBSZ * SSN)    // 32768

typedef __nv_bfloat16 bf16;

// ---------------------------------------------------------------------------
// Scratch (device globals; no allocation allowed)
// ---------------------------------------------------------------------------
__device__ __align__(16) bf16 g_act_hi[MKV * EE];
__device__ __align__(16) bf16 g_act_lo[MKV * EE];
__device__ __align__(16) bf16 g_Qh[MQ * EE];
__device__ __align__(16) bf16 g_Ql[MQ * EE];
__device__ __align__(16) bf16 g_Kh[MKV * EE];
__device__ __align__(16) bf16 g_Kl[MKV * EE];
__device__ __align__(16) bf16 g_Vh[MKV * EE];
__device__ __align__(16) bf16 g_Vl[MKV * EE];
__device__ __align__(16) bf16 g_Ch[MQ * EE];
__device__ __align__(16) bf16 g_Cl[MQ * EE];
__device__ __align__(16) bf16 g_w_hi[4][EE * EE];
__device__ __align__(16) bf16 g_w_lo[4][EE * EE];
__device__ __align__(16) unsigned char g_msk[(size_t)BBSZ * PPN * SSN];

// ---------------------------------------------------------------------------
// Small helpers
// ---------------------------------------------------------------------------
__device__ __forceinline__ uint32_t smem_u32(const void* p) {
    uint32_t a;
    asm("{ .reg .u64 t; cvta.to.shared.u64 t, %1; cvt.u32.u64 %0, t; }"
        : "=r"(a) : "l"(p));
    return a;
}
__device__ __forceinline__ void ldsm_x4(uint32_t& r0, uint32_t& r1,
                                        uint32_t& r2, uint32_t& r3, uint32_t a) {
    asm volatile("ldmatrix.sync.aligned.m8n8.x4.shared.b16 {%0,%1,%2,%3}, [%4];"
                 : "=r"(r0), "=r"(r1), "=r"(r2), "=r"(r3) : "r"(a));
}
__device__ __forceinline__ void ldsm_x4_t(uint32_t& r0, uint32_t& r1,
                                          uint32_t& r2, uint32_t& r3, uint32_t a) {
    asm volatile("ldmatrix.sync.aligned.m8n8.x4.trans.shared.b16 {%0,%1,%2,%3}, [%4];"
                 : "=r"(r0), "=r"(r1), "=r"(r2), "=r"(r3) : "r"(a));
}
__device__ __forceinline__ void mma_bf16(float* c, const uint32_t* a,
                                         uint32_t b0, uint32_t b1) {
    asm volatile(
        "mma.sync.aligned.m16n8k16.row.col.f32.bf16.bf16.f32 "
        "{%0,%1,%2,%3}, {%4,%5,%6,%7}, {%8,%9}, {%0,%1,%2,%3};"
        : "+f"(c[0]), "+f"(c[1]), "+f"(c[2]), "+f"(c[3])
        : "r"(a[0]), "r"(a[1]), "r"(a[2]), "r"(a[3]), "r"(b0), "r"(b1));
}
__device__ __forceinline__ void cp16(uint32_t dst, const void* src) {
    asm volatile("cp.async.cg.shared.global [%0], [%1], 16;"
                 :: "r"(dst), "l"(src) : "memory");
}
__device__ __forceinline__ void split2(float a, float b, uint32_t& h, uint32_t& l) {
    __nv_bfloat162 H, L;
    H.x = __float2bfloat16(a);
    H.y = __float2bfloat16(b);
    L.x = __float2bfloat16(a - __bfloat162float(H.x));
    L.y = __float2bfloat16(b - __bfloat162float(H.y));
    h = *reinterpret_cast<uint32_t*>(&H);
    l = *reinterpret_cast<uint32_t*>(&L);
}

// ---------------------------------------------------------------------------
// fp32 -> bf16 hi/lo split (vectorized x4)
// ---------------------------------------------------------------------------
__global__ void convert_split(const float* __restrict__ X,
                              bf16* __restrict__ H, bf16* __restrict__ L, int n4)
{
    int i = blockIdx.x * blockDim.x + threadIdx.x;
    if (i >= n4) return;
    float4 x = ((const float4*)X)[i];
    uint32_t h0, l0, h1, l1;
    split2(x.x, x.y, h0, l0);
    split2(x.z, x.w, h1, l1);
    ((uint32_t*)H)[2 * i] = h0; ((uint32_t*)H)[2 * i + 1] = h1;
    ((uint32_t*)L)[2 * i] = l0; ((uint32_t*)L)[2 * i + 1] = l1;
}

// mask int32 -> uint8
__global__ void pack_mask(const int* __restrict__ m,
                          unsigned char* __restrict__ o, int n4)
{
    int i = blockIdx.x * blockDim.x + threadIdx.x;
    if (i >= n4) return;
    int4 v = ((const int4*)m)[i];
    uchar4 u = {(unsigned char)v.x, (unsigned char)v.y,
                (unsigned char)v.z, (unsigned char)v.w};
    ((uchar4*)o)[i] = u;
}

// ---------------------------------------------------------------------------
// Tensor-core GEMM: C[M,512] = A[M,512] @ W[512,512]^T
// fp32 via bf16 3-term split (K_eff = 1536). CTA 128x128, 8 warps.
// Output: fp32 (+bias) if Cf != nullptr, else bf16 hi/lo split.
// ---------------------------------------------------------------------------
#define GSM 65536

__global__ __launch_bounds__(256) void gemm_mma(
    const bf16* __restrict__ Ahi, const bf16* __restrict__ Alo,
    const bf16* __restrict__ Whi, const bf16* __restrict__ Wlo,
    const float* __restrict__ bias, float* __restrict__ Cf,
    bf16* __restrict__ Ch, bf16* __restrict__ Cl)
{
    extern __shared__ char smem[];
    const uint32_t sb = smem_u32(smem);
    const int tid = threadIdx.x;
    const int wid = tid >> 5;
    const int lane = tid & 31;
    const int wm = wid >> 2;
    const int wn = wid & 3;
    const int m0 = blockIdx.y * 128;
    const int n0 = blockIdx.x * 128;

    const int r = tid >> 1;
    const int half = tid & 1;
    uint32_t so[4];
#pragma unroll
    for (int i = 0; i < 4; i++) {
        uint32_t bo = (uint32_t)r * 128 + half * 64 + i * 16;
        so[i] = bo ^ ((bo >> 3) & 0x70);
    }

    const int lrow = lane & 15;
    const uint32_t kxor = (uint32_t)(lane & 7) << 4;
    const uint32_t khalf = (uint32_t)(lane >> 4) * 16;

    float acc[4][4][4];
#pragma unroll
    for (int i = 0; i < 4; i++)
#pragma unroll
        for (int f = 0; f < 4; f++)
#pragma unroll
            for (int c = 0; c < 4; c++) acc[i][f][c] = 0.f;

    auto issue_load = [&](int kc, int buf) {
        const int seg = kc >> 3;
        const int kb = (kc & 7) * 64;
        const bf16* Asrc = (seg == 2) ? Alo : Ahi;
        const bf16* Wsrc = (seg == 1) ? Wlo : Whi;
        const char* ag = (const char*)(Asrc + (size_t)(m0 + r) * 512 + kb) + half * 64;
        const char* bg = (const char*)(Wsrc + (size_t)(n0 + r) * 512 + kb) + half * 64;
        uint32_t abase = sb + buf * 32768;
        uint32_t bbase = abase + 16384;
#pragma unroll
        for (int i = 0; i < 4; i++) {
            cp16(abase + so[i], ag + i * 16);
            cp16(bbase + so[i], bg + i * 16);
        }
        asm volatile("cp.async.commit_group;" ::: "memory");
    };

    issue_load(0, 0);

    for (int kc = 0; kc < 24; kc++) {
        const int buf = kc & 1;
        if (kc < 23) issue_load(kc + 1, buf ^ 1);
        if (kc < 23) asm volatile("cp.async.wait_group 1;" ::: "memory");
        else         asm volatile("cp.async.wait_group 0;" ::: "memory");
        __syncthreads();

        const uint32_t abase = sb + buf * 32768;
        const uint32_t bbase = abase + 16384;
#pragma unroll
        for (int ks = 0; ks < 4; ks++) {
            const uint32_t kpart = ((uint32_t)(ks * 32) + khalf) ^ kxor;
            uint32_t a[4][4];
#pragma unroll
            for (int im = 0; im < 4; im++) {
                uint32_t addr = abase + (uint32_t)(wm * 64 + im * 16 + lrow) * 128 + kpart;
                ldsm_x4(a[im][0], a[im][1], a[im][2], a[im][3], addr);
            }
            uint32_t b[2][4];
#pragma unroll
            for (int nb = 0; nb < 2; nb++) {
                uint32_t addr = bbase + (uint32_t)(wn * 32 + nb * 16 + lrow) * 128 + kpart;
                ldsm_x4(b[nb][0], b[nb][1], b[nb][2], b[nb][3], addr);
            }
#pragma unroll
            for (int im = 0; im < 4; im++)
#pragma unroll
                for (int f = 0; f < 4; f++)
                    mma_bf16(acc[im][f], a[im],
                             b[f >> 1][f & 1], b[f >> 1][(f & 1) + 2]);
        }
        __syncthreads();
    }

    const int crow = lane >> 2;
    const int ccol = (lane & 3) * 2;
#pragma unroll
    for (int im = 0; im < 4; im++) {
#pragma unroll
        for (int f = 0; f < 4; f++) {
            int row = m0 + wm * 64 + im * 16 + crow;
            int col = n0 + wn * 32 + (f >> 1) * 16 + (f & 1) * 8 + ccol;
            if (Cf) {
                float b0 = bias ? bias[col] : 0.f;
                float b1 = bias ? bias[col + 1] : 0.f;
                float2 v0 = {acc[im][f][0] + b0, acc[im][f][1] + b1};
                float2 v1 = {acc[im][f][2] + b0, acc[im][f][3] + b1};
                *(float2*)&Cf[(size_t)row * 512 + col] = v0;
                *(float2*)&Cf[(size_t)(row + 8) * 512 + col] = v1;
            } else {
                uint32_t hp, lp;
                split2(acc[im][f][0], acc[im][f][1], hp, lp);
                *(uint32_t*)&Ch[(size_t)row * 512 + col] = hp;
                *(uint32_t*)&Cl[(size_t)row * 512 + col] = lp;
                split2(acc[im][f][2], acc[im][f][3], hp, lp);
                *(uint32_t*)&Ch[(size_t)(row + 8) * 512 + col] = hp;
                *(uint32_t*)&Cl[(size_t)(row + 8) * 512 + col] = lp;
            }
        }
    }
}

// ---------------------------------------------------------------------------
// Tensor-core flash attention.
// CTA: 128 q-rows x one (b,h); 8 warps, warp = 16 rows. S-tiles of 64.
// Scores: 3-term split QK; P split in registers; PV: 3-term split P,V.
// K/V/mask tiles double-buffered via cp.async. ctx written as bf16 hi/lo.
// ---------------------------------------------------------------------------
#define ATT_BUF 43008   // Kh 8K | Kl 8K | Vh 8K | Vl 8K | msk 128*80
#define ATT_SM  (32768 + 2 * ATT_BUF)

__global__ __launch_bounds__(256) void flash_tc(
    const bf16* __restrict__ Qh_g, const bf16* __restrict__ Ql_g,
    const bf16* __restrict__ Kh_g, const bf16* __restrict__ Kl_g,
    const bf16* __restrict__ Vh_g, const bf16* __restrict__ Vl_g,
    const unsigned char* __restrict__ msk_g,
    bf16* __restrict__ Ch_g, bf16* __restrict__ Cl_g)
{
    extern __shared__ char smem[];
    const uint32_t sb = smem_u32(smem);
    const int tid = threadIdx.x;
    const int wid = tid >> 5;
    const int lane = tid & 31;
    const int b = blockIdx.y >> 3;
    const int hd = blockIdx.y & 7;
    const int p0 = blockIdx.x * 128;

    const int lrow = lane & 15;
    const uint32_t kxor = (uint32_t)(lane & 7) << 4;
    const uint32_t khalf = (uint32_t)(lane >> 4) * 16;

    // ---- Q load addressing (rows 128, 128B rows, swizzled) ----
    const int qr = tid >> 1;
    const int qhalf = tid & 1;
    uint32_t qso[4];
#pragma unroll
    for (int i = 0; i < 4; i++) {
        uint32_t bo = (uint32_t)qr * 128 + qhalf * 64 + i * 16;
        qso[i] = bo ^ ((bo >> 3) & 0x70);
    }
    {
        const char* sq_h = (const char*)(Qh_g + (size_t)(b * PPN + p0 + qr) * 512 + hd * 64)
                           + qhalf * 64;
        const char* sq_l = (const char*)(Ql_g + (size_t)(b * PPN + p0 + qr) * 512 + hd * 64)
                           + qhalf * 64;
#pragma unroll
        for (int i = 0; i < 4; i++) {
            cp16(sb + qso[i], sq_h + i * 16);
            cp16(sb + 16384 + qso[i], sq_l + i * 16);
        }
    }

    // ---- K/V tile addressing (rows 64) ----
    const int kvr = tid >> 2;
    const int kvq = tid & 3;
    uint32_t kvsw0, kvsw1;
    {
        uint32_t bo0 = (uint32_t)kvr * 128 + kvq * 32;
        uint32_t bo1 = bo0 + 16;
        kvsw0 = bo0 ^ ((bo0 >> 3) & 0x70);
        kvsw1 = bo1 ^ ((bo1 >> 3) & 0x70);
    }
    // mask: 2 chunks per thread; row = tid>>1, parts (tid&1)*2, +1
    const int mr = tid >> 1;
    const int mp = (tid & 1) * 2;

    auto issue_tile = [&](int t) {
        const uint32_t bufo = sb + 32768 + (uint32_t)(t & 1) * ATT_BUF;
        const int s0 = t * 64;
        const size_t kvrow = (size_t)(b * SSN + s0 + kvr) * 512 + hd * 64;
        const char* srcKh = (const char*)(Kh_g + kvrow) + kvq * 32;
        const char* srcKl = (const char*)(Kl_g + kvrow) + kvq * 32;
        const char* srcVh = (const char*)(Vh_g + kvrow) + kvq * 32;
        const char* srcVl = (const char*)(Vl_g + kvrow) + kvq * 32;
        cp16(bufo + kvsw0, srcKh);          cp16(bufo + kvsw1, srcKh + 16);
        cp16(bufo + 8192 + kvsw0, srcKl);   cp16(bufo + 8192 + kvsw1, srcKl + 16);
        cp16(bufo + 16384 + kvsw0, srcVh);  cp16(bufo + 16384 + kvsw1, srcVh + 16);
        cp16(bufo + 24576 + kvsw0, srcVl);  cp16(bufo + 24576 + kvsw1, srcVl + 16);
        const unsigned char* srcM = msk_g + (size_t)(b * PPN + p0 + mr) * SSN + s0;
        cp16(bufo + 32768 + (uint32_t)mr * 80 + mp * 16, srcM + mp * 16);
        cp16(bufo + 32768 + (uint32_t)mr * 80 + (mp + 1) * 16, srcM + (mp + 1) * 16);
        asm volatile("cp.async.commit_group;" ::: "memory");
    };

    issue_tile(0);

    // softmax state (registers; rows R = wid*16 + lane/4 and +8)
    float m0 = -1e30f, m1 = -1e30f, l0 = 0.f, l1 = 0.f;
    float oacc[8][4];
#pragma unroll
    for (int d = 0; d < 8; d++)
#pragma unroll
        for (int c = 0; c < 4; c++) oacc[d][c] = 0.f;

    const int r0 = lane >> 2;
    const int mcol = (lane & 3) * 2;

    for (int t = 0; t < 16; t++) {
        if (t < 15) issue_tile(t + 1);
        if (t < 15) asm volatile("cp.async.wait_group 1;" ::: "memory");
        else        asm volatile("cp.async.wait_group 0;" ::: "memory");
        __syncthreads();

        const uint32_t bufo = sb + 32768 + (uint32_t)(t & 1) * ATT_BUF;
        const uint32_t Khb = bufo, Klb = bufo + 8192;
        const uint32_t Vhb = bufo + 16384, Vlb = bufo + 24576;
        const char* mskb = smem + (bufo - sb) + 32768;

        // ---- scores ----
        float sacc[8][4];
#pragma unroll
        for (int n = 0; n < 8; n++)
#pragma unroll
            for (int c = 0; c < 4; c++) sacc[n][c] = 0.f;

#pragma unroll
        for (int kc = 0; kc < 4; kc++) {
            const uint32_t kpart = ((uint32_t)(kc * 32) + khalf) ^ kxor;
            uint32_t ah[4], al[4];
            ldsm_x4(ah[0], ah[1], ah[2], ah[3],
                    sb + (uint32_t)(wid * 16 + lrow) * 128 + kpart);
            ldsm_x4(al[0], al[1], al[2], al[3],
                    sb + 16384 + (uint32_t)(wid * 16 + lrow) * 128 + kpart);
#pragma unroll
            for (int ng = 0; ng < 4; ng++) {
                uint32_t kh[4], kl[4];
                ldsm_x4(kh[0], kh[1], kh[2], kh[3],
                        Khb + (uint32_t)(ng * 16 + lrow) * 128 + kpart);
                ldsm_x4(kl[0], kl[1], kl[2], kl[3],
                        Klb + (uint32_t)(ng * 16 + lrow) * 128 + kpart);
                mma_bf16(sacc[2 * ng], ah, kh[0], kh[2]);
                mma_bf16(sacc[2 * ng], ah, kl[0], kl[2]);
                mma_bf16(sacc[2 * ng], al, kh[0], kh[2]);
                mma_bf16(sacc[2 * ng + 1], ah, kh[1], kh[3]);
                mma_bf16(sacc[2 * ng + 1], ah, kl[1], kl[3]);
                mma_bf16(sacc[2 * ng + 1], al, kh[1], kh[3]);
            }
        }

        // ---- mask + online softmax ----
        const float scale = 0.125f;
        float mx0 = -1e30f, mx1 = -1e30f;
#pragma unroll
        for (int nb = 0; nb < 8; nb++) {
            unsigned short mm0 = *(const unsigned short*)
                (mskb + (wid * 16 + r0) * 80 + nb * 8 + mcol);
            unsigned short mm1 = *(const unsigned short*)
                (mskb + (wid * 16 + r0 + 8) * 80 + nb * 8 + mcol);
            float* s = sacc[nb];
            s[0] = (mm0 & 0xFF) ? -1e30f : s[0] * scale;
            s[1] = (mm0 >> 8)   ? -1e30f : s[1] * scale;
            s[2] = (mm1 & 0xFF) ? -1e30f : s[2] * scale;
            s[3] = (mm1 >> 8)   ? -1e30f : s[3] * scale;
            mx0 = fmaxf(mx0, fmaxf(s[0], s[1]));
            mx1 = fmaxf(mx1, fmaxf(s[2], s[3]));
        }
        mx0 = fmaxf(mx0, __shfl_xor_sync(0xffffffffu, mx0, 1));
        mx0 = fmaxf(mx0, __shfl_xor_sync(0xffffffffu, mx0, 2));
        mx1 = fmaxf(mx1, __shfl_xor_sync(0xffffffffu, mx1, 1));
        mx1 = fmaxf(mx1, __shfl_xor_sync(0xffffffffu, mx1, 2));
        float mn0 = fmaxf(m0, mx0), mn1 = fmaxf(m1, mx1);
        float f0 = __expf(m0 - mn0), f1 = __expf(m1 - mn1);
        m0 = mn0; m1 = mn1;
        float sum0 = 0.f, sum1 = 0.f;
#pragma unroll
        for (int nb = 0; nb < 8; nb++) {
            float* s = sacc[nb];
            s[0] = __expf(s[0] - mn0); s[1] = __expf(s[1] - mn0);
            s[2] = __expf(s[2] - mn1); s[3] = __expf(s[3] - mn1);
            sum0 += s[0] + s[1];
            sum1 += s[2] + s[3];
        }
        sum0 += __shfl_xor_sync(0xffffffffu, sum0, 1);
        sum0 += __shfl_xor_sync(0xffffffffu, sum0, 2);
        sum1 += __shfl_xor_sync(0xffffffffu, sum1, 1);
        sum1 += __shfl_xor_sync(0xffffffffu, sum1, 2);
        l0 = f0 * l0 + sum0;
        l1 = f1 * l1 + sum1;
#pragma unroll
        for (int d = 0; d < 8; d++) {
            oacc[d][0] *= f0; oacc[d][1] *= f0;
            oacc[d][2] *= f1; oacc[d][3] *= f1;
        }

        // ---- pack P to bf16 hi/lo A-fragments ----
        uint32_t ph[4][4], pl[4][4];
#pragma unroll
        for (int kc = 0; kc < 4; kc++) {
            float* pe = sacc[2 * kc];
            float* po = sacc[2 * kc + 1];
            split2(pe[0], pe[1], ph[kc][0], pl[kc][0]);
            split2(pe[2], pe[3], ph[kc][1], pl[kc][1]);
            split2(po[0], po[1], ph[kc][2], pl[kc][2]);
            split2(po[2], po[3], ph[kc][3], pl[kc][3]);
        }

        // ---- P @ V ----
#pragma unroll
        for (int kc = 0; kc < 4; kc++) {
            const uint32_t srow = (uint32_t)(kc * 16 + lrow) * 128;
#pragma unroll
            for (int db = 0; db < 4; db++) {
                const uint32_t dpart = ((uint32_t)(db * 32) + khalf) ^ kxor;
                uint32_t vh[4], vl[4];
                ldsm_x4_t(vh[0], vh[1], vh[2], vh[3], Vhb + srow + dpart);
                ldsm_x4_t(vl[0], vl[1], vl[2], vl[3], Vlb + srow + dpart);
                mma_bf16(oacc[2 * db], ph[kc], vh[0], vh[1]);
                mma_bf16(oacc[2 * db], ph[kc], vl[0], vl[1]);
                mma_bf16(oacc[2 * db], pl[kc], vh[0], vh[1]);
                mma_bf16(oacc[2 * db + 1], ph[kc], vh[2], vh[3]);
                mma_bf16(oacc[2 * db + 1], ph[kc], vl[2], vl[3]);
                mma_bf16(oacc[2 * db + 1], pl[kc], vh[2], vh[3]);
            }
        }
        __syncthreads();
    }

    // ---- epilogue: normalize, split, store ctx ----
    const float inv0 = 1.f / l0;
    const float inv1 = 1.f / l1;
    const size_t rowA = (size_t)(b * PPN + p0 + wid * 16 + r0) * 512 + hd * 64;
    const size_t rowB = rowA + (size_t)8 * 512;
#pragma unroll
    for (int d = 0; d < 8; d++) {
        uint32_t hp, lp;
        split2(oacc[d][0] * inv0, oacc[d][1] * inv0, hp, lp);
        *(uint32_t*)&Ch_g[rowA + d * 8 + mcol] = hp;
        *(uint32_t*)&Cl_g[rowA + d * 8 + mcol] = lp;
        split2(oacc[d][2] * inv1, oacc[d][3] * inv1, hp, lp);
        *(uint32_t*)&Ch_g[rowB + d * 8 + mcol] = hp;
        *(uint32_t*)&Cl_g[rowB + d * 8 + mcol] = lp;
    }
}

// ---------------------------------------------------------------------------
extern "C" void kernel_launch(void* const* d_in, const int* in_sizes, int n_in,
                              void* d_out, int out_size)
{
    const float* query = (const float*)d_in[0];
    const float* key   = (const float*)d_in[1];
    const float* value = (const float*)d_in[2];
    const int*   mask  = (const int*)d_in[3];
    const float* W[4]  = {(const float*)d_in[4], (const float*)d_in[5],
                          (const float*)d_in[6], (const float*)d_in[7]};
    const float* bo    = (const float*)d_in[8];
    float* out = (float*)d_out;

    bf16 *ah, *al, *wh, *wl, *qh, *ql, *kh, *kl, *vh, *vl, *ch, *cl;
    unsigned char* mk;
    cudaGetSymbolAddress((void**)&ah, g_act_hi);
    cudaGetSymbolAddress((void**)&al, g_act_lo);
    cudaGetSymbolAddress((void**)&wh, g_w_hi);
    cudaGetSymbolAddress((void**)&wl, g_w_lo);
    cudaGetSymbolAddress((void**)&qh, g_Qh);
    cudaGetSymbolAddress((void**)&ql, g_Ql);
    cudaGetSymbolAddress((void**)&kh, g_Kh);
    cudaGetSymbolAddress((void**)&kl, g_Kl);
    cudaGetSymbolAddress((void**)&vh, g_Vh);
    cudaGetSymbolAddress((void**)&vl, g_Vl);
    cudaGetSymbolAddress((void**)&ch, g_Ch);
    cudaGetSymbolAddress((void**)&cl, g_Cl);
    cudaGetSymbolAddress((void**)&mk, g_msk);

    cudaFuncSetAttribute(gemm_mma, cudaFuncAttributeMaxDynamicSharedMemorySize, GSM);
    cudaFuncSetAttribute(flash_tc, cudaFuncAttributeMaxDynamicSharedMemorySize, ATT_SM);

    dim3 blk(256);

    pack_mask<<<(BBSZ * PPN * SSN / 4 + 255) / 256, 256>>>(mask, mk,
                                                           BBSZ * PPN * SSN / 4);
    for (int w = 0; w < 4; w++)
        convert_split<<<(EE * EE / 4 + 255) / 256, 256>>>(
            W[w], wh + (size_t)w * EE * EE, wl + (size_t)w * EE * EE, EE * EE / 4);

    // Q proj -> split output
    convert_split<<<(MQ * EE / 4 + 255) / 256, 256>>>(query, ah, al, MQ * EE / 4);
    gemm_mma<<<dim3(4, MQ / 128), blk, GSM>>>(ah, al, wh, wl, nullptr,
                                              nullptr, qh, ql);
    // K proj
    convert_split<<<(MKV * EE / 4 + 255) / 256, 256>>>(key, ah, al, MKV * EE / 4);
    gemm_mma<<<dim3(4, MKV / 128), blk, GSM>>>(ah, al,
        wh + (size_t)1 * EE * EE, wl + (size_t)1 * EE * EE, nullptr,
        nullptr, kh, kl);
    // V proj
    convert_split<<<(MKV * EE / 4 + 255) / 256, 256>>>(value, ah, al, MKV * EE / 4);
    gemm_mma<<<dim3(4, MKV / 128), blk, GSM>>>(ah, al,
        wh + (size_t)2 * EE * EE, wl + (size_t)2 * EE * EE, nullptr,
        nullptr, vh, vl);

    flash_tc<<<dim3(PPN / 128, BBSZ * HH), blk, ATT_SM>>>(
        qh, ql, kh, kl, vh, vl, mk, ch, cl);

    // O proj -> fp32 out (+bias)
    gemm_mma<<<dim3(4, MQ / 128), blk, GSM>>>(ch, cl,
        wh + (size_t)3 * EE * EE, wl + (size_t)3 * EE * EE, bo,
        out, nullptr, nullptr);
}

// round 6
// speedup vs baseline: 2.6701x; 1.0214x over previous
#include <cuda_runtime.h>
#include <cuda_bf16.h>
#include <cstdint>

// Problem constants
#define EE   512
#define HH   8
#define BBSZ 32
#define PPN  512
#define SSN  1024
#define MQ   (BBSZ * PPN)    // 16384
#define MKV  (BBSZ * SSN)    // 32768

typedef __nv_bfloat16 bf16;

// ---------------------------------------------------------------------------
// Scratch (device globals; no allocation allowed)
// ---------------------------------------------------------------------------
__device__ __align__(16) bf16 g_act_hi[MKV * EE];
__device__ __align__(16) bf16 g_act_lo[MKV * EE];
__device__ __align__(16) bf16 g_Qh[MQ * EE];
__device__ __align__(16) bf16 g_Ql[MQ * EE];
__device__ __align__(16) bf16 g_Kh[MKV * EE];
__device__ __align__(16) bf16 g_Kl[MKV * EE];
__device__ __align__(16) bf16 g_Vh[MKV * EE];
__device__ __align__(16) bf16 g_Vl[MKV * EE];
__device__ __align__(16) bf16 g_Ch[MQ * EE];
__device__ __align__(16) bf16 g_Cl[MQ * EE];
__device__ __align__(16) bf16 g_w_hi[4][EE * EE];
__device__ __align__(16) bf16 g_w_lo[4][EE * EE];
__device__ __align__(16) unsigned char g_msk[(size_t)BBSZ * PPN * SSN];

// ---------------------------------------------------------------------------
// Small helpers
// ---------------------------------------------------------------------------
__device__ __forceinline__ uint32_t smem_u32(const void* p) {
    uint32_t a;
    asm("{ .reg .u64 t; cvta.to.shared.u64 t, %1; cvt.u32.u64 %0, t; }"
        : "=r"(a) : "l"(p));
    return a;
}
__device__ __forceinline__ void ldsm_x4(uint32_t& r0, uint32_t& r1,
                                        uint32_t& r2, uint32_t& r3, uint32_t a) {
    asm volatile("ldmatrix.sync.aligned.m8n8.x4.shared.b16 {%0,%1,%2,%3}, [%4];"
                 : "=r"(r0), "=r"(r1), "=r"(r2), "=r"(r3) : "r"(a));
}
__device__ __forceinline__ void ldsm_x4_t(uint32_t& r0, uint32_t& r1,
                                          uint32_t& r2, uint32_t& r3, uint32_t a) {
    asm volatile("ldmatrix.sync.aligned.m8n8.x4.trans.shared.b16 {%0,%1,%2,%3}, [%4];"
                 : "=r"(r0), "=r"(r1), "=r"(r2), "=r"(r3) : "r"(a));
}
__device__ __forceinline__ void mma_bf16(float* c, const uint32_t* a,
                                         uint32_t b0, uint32_t b1) {
    asm volatile(
        "mma.sync.aligned.m16n8k16.row.col.f32.bf16.bf16.f32 "
        "{%0,%1,%2,%3}, {%4,%5,%6,%7}, {%8,%9}, {%0,%1,%2,%3};"
        : "+f"(c[0]), "+f"(c[1]), "+f"(c[2]), "+f"(c[3])
        : "r"(a[0]), "r"(a[1]), "r"(a[2]), "r"(a[3]), "r"(b0), "r"(b1));
}
__device__ __forceinline__ void cp16(uint32_t dst, const void* src) {
    asm volatile("cp.async.cg.shared.global [%0], [%1], 16;"
                 :: "r"(dst), "l"(src) : "memory");
}
__device__ __forceinline__ void split2(float a, float b, uint32_t& h, uint32_t& l) {
    __nv_bfloat162 H, L;
    H.x = __float2bfloat16(a);
    H.y = __float2bfloat16(b);
    L.x = __float2bfloat16(a - __bfloat162float(H.x));
    L.y = __float2bfloat16(b - __bfloat162float(H.y));
    h = *reinterpret_cast<uint32_t*>(&H);
    l = *reinterpret_cast<uint32_t*>(&L);
}

// ---------------------------------------------------------------------------
// fp32 -> bf16 hi/lo split (vectorized x4)
// ---------------------------------------------------------------------------
__global__ void convert_split(const float* __restrict__ X,
                              bf16* __restrict__ H, bf16* __restrict__ L, int n4)
{
    int i = blockIdx.x * blockDim.x + threadIdx.x;
    if (i >= n4) return;
    float4 x = ((const float4*)X)[i];
    uint32_t h0, l0, h1, l1;
    split2(x.x, x.y, h0, l0);
    split2(x.z, x.w, h1, l1);
    ((uint32_t*)H)[2 * i] = h0; ((uint32_t*)H)[2 * i + 1] = h1;
    ((uint32_t*)L)[2 * i] = l0; ((uint32_t*)L)[2 * i + 1] = l1;
}

// all four weights in one launch (grid.y selects weight)
__global__ void convert_split_w(const float* __restrict__ w0,
                                const float* __restrict__ w1,
                                const float* __restrict__ w2,
                                const float* __restrict__ w3,
                                bf16* __restrict__ H, bf16* __restrict__ L, int n4)
{
    const float* src = (blockIdx.y == 0) ? w0 : (blockIdx.y == 1) ? w1
                     : (blockIdx.y == 2) ? w2 : w3;
    int i = blockIdx.x * blockDim.x + threadIdx.x;
    if (i >= n4) return;
    size_t o = (size_t)blockIdx.y * n4 + i;
    float4 x = ((const float4*)src)[i];
    uint32_t h0, l0, h1, l1;
    split2(x.x, x.y, h0, l0);
    split2(x.z, x.w, h1, l1);
    ((uint32_t*)H)[2 * o] = h0; ((uint32_t*)H)[2 * o + 1] = h1;
    ((uint32_t*)L)[2 * o] = l0; ((uint32_t*)L)[2 * o + 1] = l1;
}

// mask int32 -> uint8
__global__ void pack_mask(const int* __restrict__ m,
                          unsigned char* __restrict__ o, int n4)
{
    int i = blockIdx.x * blockDim.x + threadIdx.x;
    if (i >= n4) return;
    int4 v = ((const int4*)m)[i];
    uchar4 u = {(unsigned char)v.x, (unsigned char)v.y,
                (unsigned char)v.z, (unsigned char)v.w};
    ((uchar4*)o)[i] = u;
}

// ---------------------------------------------------------------------------
// Tensor-core GEMM: C[M,512] = A[M,512] @ W[512,512]^T
// fp32 via bf16 3-term split (K_eff = 1536). CTA 128x128, 8 warps.
// 3-stage cp.async pipeline. Output fp32(+bias) or bf16 hi/lo split.
// ---------------------------------------------------------------------------
#define GSM (3 * 32768)

__global__ __launch_bounds__(256, 2) void gemm_mma(
    const bf16* __restrict__ Ahi, const bf16* __restrict__ Alo,
    const bf16* __restrict__ Whi, const bf16* __restrict__ Wlo,
    const float* __restrict__ bias, float* __restrict__ Cf,
    bf16* __restrict__ Ch, bf16* __restrict__ Cl)
{
    extern __shared__ char smem[];
    const uint32_t sb = smem_u32(smem);
    const int tid = threadIdx.x;
    const int wid = tid >> 5;
    const int lane = tid & 31;
    const int wm = wid >> 2;
    const int wn = wid & 3;
    const int m0 = blockIdx.y * 128;
    const int n0 = blockIdx.x * 128;

    const int r = tid >> 1;
    const int half = tid & 1;
    uint32_t so[4];
#pragma unroll
    for (int i = 0; i < 4; i++) {
        uint32_t bo = (uint32_t)r * 128 + half * 64 + i * 16;
        so[i] = bo ^ ((bo >> 3) & 0x70);
    }

    const int lrow = lane & 15;
    const uint32_t kxor = (uint32_t)(lane & 7) << 4;
    const uint32_t khalf = (uint32_t)(lane >> 4) * 16;

    float acc[4][4][4];
#pragma unroll
    for (int i = 0; i < 4; i++)
#pragma unroll
        for (int f = 0; f < 4; f++)
#pragma unroll
            for (int c = 0; c < 4; c++) acc[i][f][c] = 0.f;

    auto issue_load = [&](int kc, int buf) {
        const int seg = kc >> 3;
        const int kb = (kc & 7) * 64;
        const bf16* Asrc = (seg == 2) ? Alo : Ahi;
        const bf16* Wsrc = (seg == 1) ? Wlo : Whi;
        const char* ag = (const char*)(Asrc + (size_t)(m0 + r) * 512 + kb) + half * 64;
        const char* bg = (const char*)(Wsrc + (size_t)(n0 + r) * 512 + kb) + half * 64;
        uint32_t abase = sb + (uint32_t)buf * 32768;
        uint32_t bbase = abase + 16384;
#pragma unroll
        for (int i = 0; i < 4; i++) {
            cp16(abase + so[i], ag + i * 16);
            cp16(bbase + so[i], bg + i * 16);
        }
        asm volatile("cp.async.commit_group;" ::: "memory");
    };

    issue_load(0, 0);
    issue_load(1, 1);
    issue_load(2, 2);

    int buf = 0;
    for (int kc = 0; kc < 24; kc++) {
        if (kc < 22)      asm volatile("cp.async.wait_group 2;" ::: "memory");
        else if (kc == 22) asm volatile("cp.async.wait_group 1;" ::: "memory");
        else               asm volatile("cp.async.wait_group 0;" ::: "memory");
        __syncthreads();

        const uint32_t abase = sb + (uint32_t)buf * 32768;
        const uint32_t bbase = abase + 16384;
#pragma unroll
        for (int ks = 0; ks < 4; ks++) {
            const uint32_t kpart = ((uint32_t)(ks * 32) + khalf) ^ kxor;
            uint32_t a[4][4];
#pragma unroll
            for (int im = 0; im < 4; im++) {
                uint32_t addr = abase + (uint32_t)(wm * 64 + im * 16 + lrow) * 128 + kpart;
                ldsm_x4(a[im][0], a[im][1], a[im][2], a[im][3], addr);
            }
            uint32_t b[2][4];
#pragma unroll
            for (int nb = 0; nb < 2; nb++) {
                uint32_t addr = bbase + (uint32_t)(wn * 32 + nb * 16 + lrow) * 128 + kpart;
                ldsm_x4(b[nb][0], b[nb][1], b[nb][2], b[nb][3], addr);
            }
#pragma unroll
            for (int im = 0; im < 4; im++)
#pragma unroll
                for (int f = 0; f < 4; f++)
                    mma_bf16(acc[im][f], a[im],
                             b[f >> 1][f & 1], b[f >> 1][(f & 1) + 2]);
        }
        __syncthreads();
        if (kc + 3 < 24) issue_load(kc + 3, buf);
        buf = (buf == 2) ? 0 : buf + 1;
    }

    const int crow = lane >> 2;
    const int ccol = (lane & 3) * 2;
#pragma unroll
    for (int im = 0; im < 4; im++) {
#pragma unroll
        for (int f = 0; f < 4; f++) {
            int row = m0 + wm * 64 + im * 16 + crow;
            int col = n0 + wn * 32 + (f >> 1) * 16 + (f & 1) * 8 + ccol;
            if (Cf) {
                float b0 = bias ? bias[col] : 0.f;
                float b1 = bias ? bias[col + 1] : 0.f;
                float2 v0 = {acc[im][f][0] + b0, acc[im][f][1] + b1};
                float2 v1 = {acc[im][f][2] + b0, acc[im][f][3] + b1};
                *(float2*)&Cf[(size_t)row * 512 + col] = v0;
                *(float2*)&Cf[(size_t)(row + 8) * 512 + col] = v1;
            } else {
                uint32_t hp, lp;
                split2(acc[im][f][0], acc[im][f][1], hp, lp);
                *(uint32_t*)&Ch[(size_t)row * 512 + col] = hp;
                *(uint32_t*)&Cl[(size_t)row * 512 + col] = lp;
                split2(acc[im][f][2], acc[im][f][3], hp, lp);
                *(uint32_t*)&Ch[(size_t)(row + 8) * 512 + col] = hp;
                *(uint32_t*)&Cl[(size_t)(row + 8) * 512 + col] = lp;
            }
        }
    }
}

// ---------------------------------------------------------------------------
// Tensor-core flash attention.
// CTA: 128 q-rows x one (b,h); 8 warps; S-tiles of 64; single KV buffer,
// 2 CTAs/SM for latency hiding. ctx written as bf16 hi/lo.
// ---------------------------------------------------------------------------
#define ATT_BUF 43008   // Kh 8K | Kl 8K | Vh 8K | Vl 8K | msk 128*80
#define ATT_SM  (32768 + ATT_BUF)   // + Q hi/lo

__global__ __launch_bounds__(256, 2) void flash_tc(
    const bf16* __restrict__ Qh_g, const bf16* __restrict__ Ql_g,
    const bf16* __restrict__ Kh_g, const bf16* __restrict__ Kl_g,
    const bf16* __restrict__ Vh_g, const bf16* __restrict__ Vl_g,
    const unsigned char* __restrict__ msk_g,
    bf16* __restrict__ Ch_g, bf16* __restrict__ Cl_g)
{
    extern __shared__ char smem[];
    const uint32_t sb = smem_u32(smem);
    const int tid = threadIdx.x;
    const int wid = tid >> 5;
    const int lane = tid & 31;
    const int b = blockIdx.y >> 3;
    const int hd = blockIdx.y & 7;
    const int p0 = blockIdx.x * 128;

    const int lrow = lane & 15;
    const uint32_t kxor = (uint32_t)(lane & 7) << 4;
    const uint32_t khalf = (uint32_t)(lane >> 4) * 16;

    // ---- Q load addressing ----
    const int qr = tid >> 1;
    const int qhalf = tid & 1;
    uint32_t qso[4];
#pragma unroll
    for (int i = 0; i < 4; i++) {
        uint32_t bo = (uint32_t)qr * 128 + qhalf * 64 + i * 16;
        qso[i] = bo ^ ((bo >> 3) & 0x70);
    }
    {
        const char* sq_h = (const char*)(Qh_g + (size_t)(b * PPN + p0 + qr) * 512 + hd * 64)
                           + qhalf * 64;
        const char* sq_l = (const char*)(Ql_g + (size_t)(b * PPN + p0 + qr) * 512 + hd * 64)
                           + qhalf * 64;
#pragma unroll
        for (int i = 0; i < 4; i++) {
            cp16(sb + qso[i], sq_h + i * 16);
            cp16(sb + 16384 + qso[i], sq_l + i * 16);
        }
    }

    // ---- K/V tile addressing ----
    const int kvr = tid >> 2;
    const int kvq = tid & 3;
    uint32_t kvsw0, kvsw1;
    {
        uint32_t bo0 = (uint32_t)kvr * 128 + kvq * 32;
        uint32_t bo1 = bo0 + 16;
        kvsw0 = bo0 ^ ((bo0 >> 3) & 0x70);
        kvsw1 = bo1 ^ ((bo1 >> 3) & 0x70);
    }
    const int mr = tid >> 1;
    const int mp = (tid & 1) * 2;

    const uint32_t bufo = sb + 32768;
    auto issue_tile = [&](int t) {
        const int s0 = t * 64;
        const size_t kvrow = (size_t)(b * SSN + s0 + kvr) * 512 + hd * 64;
        const char* srcKh = (const char*)(Kh_g + kvrow) + kvq * 32;
        const char* srcKl = (const char*)(Kl_g + kvrow) + kvq * 32;
        const char* srcVh = (const char*)(Vh_g + kvrow) + kvq * 32;
        const char* srcVl = (const char*)(Vl_g + kvrow) + kvq * 32;
        cp16(bufo + kvsw0, srcKh);          cp16(bufo + kvsw1, srcKh + 16);
        cp16(bufo + 8192 + kvsw0, srcKl);   cp16(bufo + 8192 + kvsw1, srcKl + 16);
        cp16(bufo + 16384 + kvsw0, srcVh);  cp16(bufo + 16384 + kvsw1, srcVh + 16);
        cp16(bufo + 24576 + kvsw0, srcVl);  cp16(bufo + 24576 + kvsw1, srcVl + 16);
        const unsigned char* srcM = msk_g + (size_t)(b * PPN + p0 + mr) * SSN + s0;
        cp16(bufo + 32768 + (uint32_t)mr * 80 + mp * 16, srcM + mp * 16);
        cp16(bufo + 32768 + (uint32_t)mr * 80 + (mp + 1) * 16, srcM + (mp + 1) * 16);
        asm volatile("cp.async.commit_group;" ::: "memory");
    };

    issue_tile(0);
    asm volatile("cp.async.wait_group 0;" ::: "memory");
    __syncthreads();

    float m0 = -1e30f, m1 = -1e30f, l0 = 0.f, l1 = 0.f;
    float oacc[8][4];
#pragma unroll
    for (int d = 0; d < 8; d++)
#pragma unroll
        for (int c = 0; c < 4; c++) oacc[d][c] = 0.f;

    const int r0 = lane >> 2;
    const int mcol = (lane & 3) * 2;

    const uint32_t Khb = bufo, Klb = bufo + 8192;
    const uint32_t Vhb = bufo + 16384, Vlb = bufo + 24576;
    const char* mskb = smem + 32768 + 32768;

    for (int t = 0; t < 16; t++) {
        // ---- scores ----
        float sacc[8][4];
#pragma unroll
        for (int n = 0; n < 8; n++)
#pragma unroll
            for (int c = 0; c < 4; c++) sacc[n][c] = 0.f;

#pragma unroll
        for (int kc = 0; kc < 4; kc++) {
            const uint32_t kpart = ((uint32_t)(kc * 32) + khalf) ^ kxor;
            uint32_t ah[4], al[4];
            ldsm_x4(ah[0], ah[1], ah[2], ah[3],
                    sb + (uint32_t)(wid * 16 + lrow) * 128 + kpart);
            ldsm_x4(al[0], al[1], al[2], al[3],
                    sb + 16384 + (uint32_t)(wid * 16 + lrow) * 128 + kpart);
#pragma unroll
            for (int ng = 0; ng < 4; ng++) {
                uint32_t kh[4], kl[4];
                ldsm_x4(kh[0], kh[1], kh[2], kh[3],
                        Khb + (uint32_t)(ng * 16 + lrow) * 128 + kpart);
                ldsm_x4(kl[0], kl[1], kl[2], kl[3],
                        Klb + (uint32_t)(ng * 16 + lrow) * 128 + kpart);
                mma_bf16(sacc[2 * ng], ah, kh[0], kh[2]);
                mma_bf16(sacc[2 * ng], ah, kl[0], kl[2]);
                mma_bf16(sacc[2 * ng], al, kh[0], kh[2]);
                mma_bf16(sacc[2 * ng + 1], ah, kh[1], kh[3]);
                mma_bf16(sacc[2 * ng + 1], ah, kl[1], kl[3]);
                mma_bf16(sacc[2 * ng + 1], al, kh[1], kh[3]);
            }
        }

        // ---- mask + online softmax ----
        const float scale = 0.125f;
        float mx0 = -1e30f, mx1 = -1e30f;
#pragma unroll
        for (int nb = 0; nb < 8; nb++) {
            unsigned short mm0 = *(const unsigned short*)
                (mskb + (wid * 16 + r0) * 80 + nb * 8 + mcol);
            unsigned short mm1 = *(const unsigned short*)
                (mskb + (wid * 16 + r0 + 8) * 80 + nb * 8 + mcol);
            float* s = sacc[nb];
            s[0] = (mm0 & 0xFF) ? -1e30f : s[0] * scale;
            s[1] = (mm0 >> 8)   ? -1e30f : s[1] * scale;
            s[2] = (mm1 & 0xFF) ? -1e30f : s[2] * scale;
            s[3] = (mm1 >> 8)   ? -1e30f : s[3] * scale;
            mx0 = fmaxf(mx0, fmaxf(s[0], s[1]));
            mx1 = fmaxf(mx1, fmaxf(s[2], s[3]));
        }
        mx0 = fmaxf(mx0, __shfl_xor_sync(0xffffffffu, mx0, 1));
        mx0 = fmaxf(mx0, __shfl_xor_sync(0xffffffffu, mx0, 2));
        mx1 = fmaxf(mx1, __shfl_xor_sync(0xffffffffu, mx1, 1));
        mx1 = fmaxf(mx1, __shfl_xor_sync(0xffffffffu, mx1, 2));
        float mn0 = fmaxf(m0, mx0), mn1 = fmaxf(m1, mx1);
        float f0 = __expf(m0 - mn0), f1 = __expf(m1 - mn1);
        m0 = mn0; m1 = mn1;
        float sum0 = 0.f, sum1 = 0.f;
#pragma unroll
        for (int nb = 0; nb < 8; nb++) {
            float* s = sacc[nb];
            s[0] = __expf(s[0] - mn0); s[1] = __expf(s[1] - mn0);
            s[2] = __expf(s[2] - mn1); s[3] = __expf(s[3] - mn1);
            sum0 += s[0] + s[1];
            sum1 += s[2] + s[3];
        }
        sum0 += __shfl_xor_sync(0xffffffffu, sum0, 1);
        sum0 += __shfl_xor_sync(0xffffffffu, sum0, 2);
        sum1 += __shfl_xor_sync(0xffffffffu, sum1, 1);
        sum1 += __shfl_xor_sync(0xffffffffu, sum1, 2);
        l0 = f0 * l0 + sum0;
        l1 = f1 * l1 + sum1;
#pragma unroll
        for (int d = 0; d < 8; d++) {
            oacc[d][0] *= f0; oacc[d][1] *= f0;
            oacc[d][2] *= f1; oacc[d][3] *= f1;
        }

        // ---- P @ V (P hi/lo packed per kc; short live ranges) ----
#pragma unroll
        for (int kc = 0; kc < 4; kc++) {
            uint32_t ph[4], pl[4];
            float* pe = sacc[2 * kc];
            float* po = sacc[2 * kc + 1];
            split2(pe[0], pe[1], ph[0], pl[0]);
            split2(pe[2], pe[3], ph[1], pl[1]);
            split2(po[0], po[1], ph[2], pl[2]);
            split2(po[2], po[3], ph[3], pl[3]);
            const uint32_t srow = (uint32_t)(kc * 16 + lrow) * 128;
#pragma unroll
            for (int db = 0; db < 4; db++) {
                const uint32_t dpart = ((uint32_t)(db * 32) + khalf) ^ kxor;
                uint32_t vh[4], vl[4];
                ldsm_x4_t(vh[0], vh[1], vh[2], vh[3], Vhb + srow + dpart);
                ldsm_x4_t(vl[0], vl[1], vl[2], vl[3], Vlb + srow + dpart);
                mma_bf16(oacc[2 * db], ph, vh[0], vh[1]);
                mma_bf16(oacc[2 * db], ph, vl[0], vl[1]);
                mma_bf16(oacc[2 * db], pl, vh[0], vh[1]);
                mma_bf16(oacc[2 * db + 1], ph, vh[2], vh[3]);
                mma_bf16(oacc[2 * db + 1], ph, vl[2], vl[3]);
                mma_bf16(oacc[2 * db + 1], pl, vh[2], vh[3]);
            }
        }

        if (t < 15) {
            __syncthreads();           // all warps done with buffer
            issue_tile(t + 1);
            asm volatile("cp.async.wait_group 0;" ::: "memory");
            __syncthreads();
        }
    }

    // ---- epilogue: normalize, split, store ctx ----
    const float inv0 = 1.f / l0;
    const float inv1 = 1.f / l1;
    const size_t rowA = (size_t)(b * PPN + p0 + wid * 16 + r0) * 512 + hd * 64;
    const size_t rowB = rowA + (size_t)8 * 512;
#pragma unroll
    for (int d = 0; d < 8; d++) {
        uint32_t hp, lp;
        split2(oacc[d][0] * inv0, oacc[d][1] * inv0, hp, lp);
        *(uint32_t*)&Ch_g[rowA + d * 8 + mcol] = hp;
        *(uint32_t*)&Cl_g[rowA + d * 8 + mcol] = lp;
        split2(oacc[d][2] * inv1, oacc[d][3] * inv1, hp, lp);
        *(uint32_t*)&Ch_g[rowB + d * 8 + mcol] = hp;
        *(uint32_t*)&Cl_g[rowB + d * 8 + mcol] = lp;
    }
}

// ---------------------------------------------------------------------------
extern "C" void kernel_launch(void* const* d_in, const int* in_sizes, int n_in,
                              void* d_out, int out_size)
{
    const float* query = (const float*)d_in[0];
    const float* key   = (const float*)d_in[1];
    const float* value = (const float*)d_in[2];
    const int*   mask  = (const int*)d_in[3];
    const float* W[4]  = {(const float*)d_in[4], (const float*)d_in[5],
                          (const float*)d_in[6], (const float*)d_in[7]};
    const float* bo    = (const float*)d_in[8];
    float* out = (float*)d_out;

    bf16 *ah, *al, *wh, *wl, *qh, *ql, *kh, *kl, *vh, *vl, *ch, *cl;
    unsigned char* mk;
    cudaGetSymbolAddress((void**)&ah, g_act_hi);
    cudaGetSymbolAddress((void**)&al, g_act_lo);
    cudaGetSymbolAddress((void**)&wh, g_w_hi);
    cudaGetSymbolAddress((void**)&wl, g_w_lo);
    cudaGetSymbolAddress((void**)&qh, g_Qh);
    cudaGetSymbolAddress((void**)&ql, g_Ql);
    cudaGetSymbolAddress((void**)&kh, g_Kh);
    cudaGetSymbolAddress((void**)&kl, g_Kl);
    cudaGetSymbolAddress((void**)&vh, g_Vh);
    cudaGetSymbolAddress((void**)&vl, g_Vl);
    cudaGetSymbolAddress((void**)&ch, g_Ch);
    cudaGetSymbolAddress((void**)&cl, g_Cl);
    cudaGetSymbolAddress((void**)&mk, g_msk);

    cudaFuncSetAttribute(gemm_mma, cudaFuncAttributeMaxDynamicSharedMemorySize, GSM);
    cudaFuncSetAttribute(flash_tc, cudaFuncAttributeMaxDynamicSharedMemorySize, ATT_SM);

    dim3 blk(256);

    pack_mask<<<(BBSZ * PPN * SSN / 4 + 255) / 256, 256>>>(mask, mk,
                                                           BBSZ * PPN * SSN / 4);
    convert_split_w<<<dim3(EE * EE / 4 / 256, 4), 256>>>(
        W[0], W[1], W[2], W[3], wh, wl, EE * EE / 4);

    // Q proj -> split output
    convert_split<<<(MQ * EE / 4 + 255) / 256, 256>>>(query, ah, al, MQ * EE / 4);
    gemm_mma<<<dim3(4, MQ / 128), blk, GSM>>>(ah, al, wh, wl, nullptr,
                                              nullptr, qh, ql);
    // K proj
    convert_split<<<(MKV * EE / 4 + 255) / 256, 256>>>(key, ah, al, MKV * EE / 4);
    gemm_mma<<<dim3(4, MKV / 128), blk, GSM>>>(ah, al,
        wh + (size_t)1 * EE * EE, wl + (size_t)1 * EE * EE, nullptr,
        nullptr, kh, kl);
    // V proj
    convert_split<<<(MKV * EE / 4 + 255) / 256, 256>>>(value, ah, al, MKV * EE / 4);
    gemm_mma<<<dim3(4, MKV / 128), blk, GSM>>>(ah, al,
        wh + (size_t)2 * EE * EE, wl + (size_t)2 * EE * EE, nullptr,
        nullptr, vh, vl);

    flash_tc<<<dim3(PPN / 128, BBSZ * HH), blk, ATT_SM>>>(
        qh, ql, kh, kl, vh, vl, mk, ch, cl);

    // O proj -> fp32 out (+bias)
    gemm_mma<<<dim3(4, MQ / 128), blk, GSM>>>(ch, cl,
        wh + (size_t)3 * EE * EE, wl + (size_t)3 * EE * EE, bo,
        out, nullptr, nullptr);
}